// round 1
// baseline (speedup 1.0000x reference)
#include <cuda_runtime.h>
#include <cstdint>

#define NN   32
#define CC   256
#define HH   56
#define WW   56
#define SS   3136        // HH*WW
#define NPOS 100352      // NN*SS
#define CS   802816      // CC*SS
#define TOT  25690112    // NN*CC*SS
#define EPSV 1e-5

// ---------------- scratch (device globals; no allocations) ----------------
__device__ unsigned  g_xb [NPOS * 8];   // packed sign bits of act1 (bit c%32 of word c/32)
__device__ unsigned  g_xb2[NPOS * 8];   // packed sign bits of act2
__device__ short     g_P  [NPOS];       // per-position channel sign-sum (act1)
__device__ short     g_T  [NPOS];       // 3x3 box sum of g_P
__device__ short     g_P2 [NPOS];       // per-position channel sign-sum (act2)
__device__ short     g_y1 [TOT];        // slow path: exact integer conv1 output
__device__ short     g_y2 [TOT];        // slow path: exact integer conv2 output
__device__ float     g_scale1[CC], g_scale2[CC];
__device__ unsigned  g_ent3[CC * 2304]; // sparse corrections (w<=0) for conv3x3
__device__ int       g_cnt3[CC];
__device__ int       g_bad3;
__device__ unsigned  g_ent1[CC * 256];  // sparse corrections for conv1x1
__device__ int       g_cnt1[CC];
__device__ int       g_bad2;
__device__ long long g_sumT, g_sumT2, g_sumP2, g_sumP2q;       // fast-path stats
__device__ long long g_s1[CC], g_s1q[CC], g_s2[CC], g_s2q[CC]; // slow-path stats
__device__ float     g_a1[CC], g_c1[CC], g_a2[CC], g_c2[CC];   // folded BN coeffs

__device__ __forceinline__ void atomAddLL(long long* p, long long v) {
    atomicAdd((unsigned long long*)p, (unsigned long long)v);
}

// ---------------- K00: zero accumulators (every replay) ----------------
__global__ void k_zero() {
    int t = threadIdx.x;
    if (t == 0) {
        g_sumT = 0; g_sumT2 = 0; g_sumP2 = 0; g_sumP2q = 0;
        g_bad3 = 0; g_bad2 = 0;
    }
    if (t < CC) {
        g_cnt3[t] = 0; g_cnt1[t] = 0;
        g_s1[t] = 0; g_s1q[t] = 0; g_s2[t] = 0; g_s2q[t] = 0;
    }
}

// ---------------- K0: weight prep (scales + sparse correction lists) ----------------
__global__ void k_wprep(const float* __restrict__ w3, const float* __restrict__ wr) {
    __shared__ float red[256];
    int b = blockIdx.x, t = threadIdx.x;
    if (b < CC) {
        int o = b;
        float s = 0.f;
        for (int j = t; j < 2304; j += 256) {
            float v = w3[o * 2304 + j];
            s += fabsf(v);
            if (v <= 0.f) {                        // sign(w) != +1
                int neg = (v < 0.f) ? 1 : 0;       // delta = sign(w)-1 : -2 (neg) or -1 (zero)
                int i = j / 9, tap = j % 9;
                int slot = atomicAdd(&g_cnt3[o], 1);
                g_ent3[o * 2304 + slot] = (unsigned)((i << 5) | (tap << 1) | neg);
                atomicAdd(&g_bad3, 1);
            }
        }
        red[t] = s; __syncthreads();
        for (int st = 128; st > 0; st >>= 1) { if (t < st) red[t] += red[t + st]; __syncthreads(); }
        if (t == 0) g_scale1[o] = red[0] / 2304.f;
    } else {
        int o = b - CC;
        float v = wr[o * 256 + t];
        float s = fabsf(v);
        if (v <= 0.f) {
            int neg = (v < 0.f) ? 1 : 0;
            int slot = atomicAdd(&g_cnt1[o], 1);
            g_ent1[o * 256 + slot] = (unsigned)((t << 1) | neg);
            atomicAdd(&g_bad2, 1);
        }
        red[t] = s; __syncthreads();
        for (int st = 128; st > 0; st >>= 1) { if (t < st) red[t] += red[t + st]; __syncthreads(); }
        if (t == 0) g_scale2[o] = red[0] / 256.f;
    }
}

// ---------------- K1: sign(x+b1_1) -> packed bits + per-position channel sum P ----------------
__global__ __launch_bounds__(256) void k_sign1(const float* __restrict__ x,
                                               const float* __restrict__ b1_1) {
    __shared__ float sb[256];
    __shared__ int   sp[8][32];
    int tx = threadIdx.x, ty = threadIdx.y, t = ty * 32 + tx;
    sb[t] = b1_1[t];
    __syncthreads();
    int p = blockIdx.x * 32 + tx;              // NPOS divisible by 32; blocks never straddle n
    int n = p / SS, s = p % SS;
    const float* xp = x + (size_t)n * CS + s;
    unsigned w = 0;
    #pragma unroll
    for (int it = 0; it < 32; it++) {
        int c = ty * 32 + it;
        float v = xp[(size_t)c * SS] + sb[c];
        w |= (unsigned)(v >= 0.f) << it;
    }
    g_xb[p * 8 + ty] = w;
    sp[ty][tx] = 2 * __popc(w) - 32;
    __syncthreads();
    if (ty == 0) {
        int P = 0;
        #pragma unroll
        for (int k = 0; k < 8; k++) P += sp[k][tx];
        g_P[p] = (short)P;
    }
}

// ---------------- K1b: 3x3 box filter T = box(P), plus exact stats of T ----------------
__global__ __launch_bounds__(256) void k_box() {
    int p = blockIdx.x * 256 + threadIdx.x;    // 392*256 == NPOS
    int n = p / SS, s = p % SS;
    int h = s / WW, w = s % WW;
    int T = 0;
    #pragma unroll
    for (int dh = -1; dh <= 1; dh++) {
        int hh = h + dh; if (hh < 0 || hh >= HH) continue;
        #pragma unroll
        for (int dw = -1; dw <= 1; dw++) {
            int ww = w + dw; if (ww < 0 || ww >= WW) continue;
            T += g_P[n * SS + hh * WW + ww];
        }
    }
    g_T[p] = (short)T;
    int v1 = T, v2 = T * T;
    #pragma unroll
    for (int m = 16; m > 0; m >>= 1) {
        v1 += __shfl_xor_sync(0xffffffffu, v1, m);
        v2 += __shfl_xor_sync(0xffffffffu, v2, m);
    }
    if ((threadIdx.x & 31) == 0) {
        atomAddLL(&g_sumT, (long long)v1);
        atomAddLL(&g_sumT2, (long long)v2);
    }
}

// ---------------- K2slow: exact conv1 (only if some w3x3 <= 0) ----------------
__global__ __launch_bounds__(256) void k_conv1_slow() {
    if (g_bad3 == 0) return;
    int o = threadIdx.x;
    int b = blockIdx.x, n = b / HH, h = b % HH;
    int cnt = g_cnt3[o];
    const unsigned* ent = &g_ent3[o * 2304];
    int accI = 0, accI2 = 0;
    for (int w = 0; w < WW; w++) {
        int p = n * SS + h * WW + w;
        int I = g_T[p];
        for (int e = 0; e < cnt; e++) {
            unsigned en = ent[e];
            int neg = en & 1, tap = (en >> 1) & 15, i = en >> 5;
            int hh = h + tap / 3 - 1, ww = w + tap % 3 - 1;
            if (hh >= 0 && hh < HH && ww >= 0 && ww < WW) {
                unsigned word = g_xb[(n * SS + hh * WW + ww) * 8 + (i >> 5)];
                int sx = ((word >> (i & 31)) & 1) ? 1 : -1;
                I += (neg ? -2 : -1) * sx;
            }
        }
        g_y1[(size_t)(n * CC + o) * SS + h * WW + w] = (short)I;
        accI += I; accI2 += I * I;
    }
    atomAddLL(&g_s1[o], (long long)accI);
    atomAddLL(&g_s1q[o], (long long)accI2);
}

// ---------------- K3: fold BN1 into per-channel affine a1*I + c1 ----------------
__global__ void k_bn1(const float* __restrict__ g, const float* __restrict__ bet) {
    int o = threadIdx.x;
    double sI, sI2;
    if (g_bad3 == 0) { sI = (double)g_sumT; sI2 = (double)g_sumT2; }
    else             { sI = (double)g_s1[o]; sI2 = (double)g_s1q[o]; }
    double mu  = sI / (double)NPOS;
    double var = sI2 / (double)NPOS - mu * mu;
    double sc  = (double)g_scale1[o];
    double a   = (double)g[o] * sc / sqrt(sc * sc * var + EPSV);
    g_a1[o] = (float)a;
    g_c1[o] = (float)((double)bet[o] - a * mu);
}

// ---------------- K4: mid elementwise -> act2 bits + P2 (+ stats of P2) ----------------
__global__ __launch_bounds__(256) void k_mid(const float* __restrict__ x,
                                             const float* __restrict__ b1_2,
                                             const float* __restrict__ p1a,
                                             const float* __restrict__ b1_3,
                                             const float* __restrict__ b2_1) {
    __shared__ float sa1[256], sc1[256], sb2[256], spa[256], sb3[256], sbb[256];
    __shared__ int sp[8][32];
    int tx = threadIdx.x, ty = threadIdx.y, t = ty * 32 + tx;
    sa1[t] = g_a1[t]; sc1[t] = g_c1[t]; sb2[t] = b1_2[t];
    spa[t] = p1a[t];  sb3[t] = b1_3[t]; sbb[t] = b2_1[t];
    __syncthreads();
    int p = blockIdx.x * 32 + tx;
    int n = p / SS, s = p % SS;
    int slow = g_bad3;
    int Tv = g_T[p];
    const float* xp = x + (size_t)n * CS + s;
    const short* yp = g_y1 + (size_t)n * CS + s;
    unsigned wrd = 0;
    #pragma unroll
    for (int it = 0; it < 32; it++) {
        int c = ty * 32 + it;
        int I = slow ? (int)yp[(size_t)c * SS] : Tv;
        float v = xp[(size_t)c * SS] + (sa1[c] * (float)I + sc1[c]) + sb2[c];
        v = (v >= 0.f) ? v : spa[c] * v;
        v += sb3[c];
        wrd |= (unsigned)((v + sbb[c]) >= 0.f) << it;
    }
    g_xb2[p * 8 + ty] = wrd;
    sp[ty][tx] = 2 * __popc(wrd) - 32;
    __syncthreads();
    if (ty == 0) {
        int P2 = 0;
        #pragma unroll
        for (int k = 0; k < 8; k++) P2 += sp[k][tx];
        g_P2[p] = (short)P2;
        int v1 = P2, v2 = P2 * P2;
        #pragma unroll
        for (int m = 16; m > 0; m >>= 1) {
            v1 += __shfl_xor_sync(0xffffffffu, v1, m);
            v2 += __shfl_xor_sync(0xffffffffu, v2, m);
        }
        if (tx == 0) {
            atomAddLL(&g_sumP2, (long long)v1);
            atomAddLL(&g_sumP2q, (long long)v2);
        }
    }
}

// ---------------- K5slow: exact conv2 (only if some wres <= 0) ----------------
__global__ __launch_bounds__(256) void k_conv2_slow() {
    if (g_bad2 == 0) return;
    int o = threadIdx.x;
    int b = blockIdx.x, n = b / HH, h = b % HH;
    int cnt = g_cnt1[o];
    const unsigned* ent = &g_ent1[o * 256];
    int accI = 0, accI2 = 0;
    for (int w = 0; w < WW; w++) {
        int p = n * SS + h * WW + w;
        int I = g_P2[p];
        for (int e = 0; e < cnt; e++) {
            unsigned en = ent[e];
            int neg = en & 1, i = en >> 1;
            unsigned word = g_xb2[p * 8 + (i >> 5)];
            int sx = ((word >> (i & 31)) & 1) ? 1 : -1;
            I += (neg ? -2 : -1) * sx;
        }
        g_y2[(size_t)(n * CC + o) * SS + h * WW + w] = (short)I;
        accI += I; accI2 += I * I;
    }
    atomAddLL(&g_s2[o], (long long)accI);
    atomAddLL(&g_s2q[o], (long long)accI2);
}

// ---------------- K6: fold BN2 ----------------
__global__ void k_bn2(const float* __restrict__ g, const float* __restrict__ bet) {
    int o = threadIdx.x;
    double sI, sI2;
    if (g_bad2 == 0) { sI = (double)g_sumP2; sI2 = (double)g_sumP2q; }
    else             { sI = (double)g_s2[o]; sI2 = (double)g_s2q[o]; }
    double mu  = sI / (double)NPOS;
    double var = sI2 / (double)NPOS - mu * mu;
    double sc  = (double)g_scale2[o];
    double a   = (double)g[o] * sc / sqrt(sc * sc * var + EPSV);
    g_a2[o] = (float)a;
    g_c2[o] = (float)((double)bet[o] - a * mu);
}

// ---------------- K7: final fused elementwise (recomputes u; no 103MB intermediate) ----------------
__global__ __launch_bounds__(256) void k_final(const float* __restrict__ x,
                                               const float* __restrict__ b1_2,
                                               const float* __restrict__ p1a,
                                               const float* __restrict__ b1_3,
                                               const float* __restrict__ b2_2,
                                               const float* __restrict__ p2a,
                                               const float* __restrict__ b2_3,
                                               float* __restrict__ out) {
    __shared__ float sa1[256], sc1[256], sb2[256], spa[256], sb3[256];
    __shared__ float sa2[256], sc2[256], sbb2[256], spa2[256], sbb3[256];
    int tx = threadIdx.x, ty = threadIdx.y, t = ty * 32 + tx;
    sa1[t] = g_a1[t]; sc1[t] = g_c1[t]; sb2[t] = b1_2[t]; spa[t] = p1a[t]; sb3[t] = b1_3[t];
    sa2[t] = g_a2[t]; sc2[t] = g_c2[t]; sbb2[t] = b2_2[t]; spa2[t] = p2a[t]; sbb3[t] = b2_3[t];
    __syncthreads();
    int p = blockIdx.x * 32 + tx;
    int n = p / SS, s = p % SS;
    int slow1 = g_bad3, slow2 = g_bad2;
    int Tv = g_T[p], P2v = g_P2[p];
    const float* xp = x + (size_t)n * CS + s;
    const short* y1p = g_y1 + (size_t)n * CS + s;
    const short* y2p = g_y2 + (size_t)n * CS + s;
    float* op = out + (size_t)n * CS + s;
    #pragma unroll
    for (int it = 0; it < 32; it++) {
        int c = ty * 32 + it;
        int I1 = slow1 ? (int)y1p[(size_t)c * SS] : Tv;
        float u = xp[(size_t)c * SS] + (sa1[c] * (float)I1 + sc1[c]) + sb2[c];
        u = (u >= 0.f) ? u : spa[c] * u;
        u += sb3[c];
        int I2 = slow2 ? (int)y2p[(size_t)c * SS] : P2v;
        float v = u + (sa2[c] * (float)I2 + sc2[c]) + sbb2[c];
        v = (v >= 0.f) ? v : spa2[c] * v;
        v += sbb3[c];
        op[(size_t)c * SS] = v;
    }
}

// ---------------- launch ----------------
extern "C" void kernel_launch(void* const* d_in, const int* in_sizes, int n_in,
                              void* d_out, int out_size) {
    const float* x     = (const float*)d_in[0];
    const float* b1_1  = (const float*)d_in[1];
    const float* w3x3  = (const float*)d_in[2];
    const float* bn1_g = (const float*)d_in[3];
    const float* bn1_b = (const float*)d_in[4];
    const float* b1_2  = (const float*)d_in[5];
    const float* p1a   = (const float*)d_in[6];
    const float* b1_3  = (const float*)d_in[7];
    const float* b2_1  = (const float*)d_in[8];
    const float* wres  = (const float*)d_in[9];
    const float* bn2_g = (const float*)d_in[10];
    const float* bn2_b = (const float*)d_in[11];
    const float* b2_2  = (const float*)d_in[12];
    const float* p2a   = (const float*)d_in[13];
    const float* b2_3  = (const float*)d_in[14];
    float* out = (float*)d_out;

    dim3 blk(32, 8);
    k_zero<<<1, 256>>>();
    k_wprep<<<512, 256>>>(w3x3, wres);
    k_sign1<<<NPOS / 32, blk>>>(x, b1_1);
    k_box<<<NPOS / 256, 256>>>();
    k_conv1_slow<<<NN * HH, 256>>>();
    k_bn1<<<1, 256>>>(bn1_g, bn1_b);
    k_mid<<<NPOS / 32, blk>>>(x, b1_2, p1a, b1_3, b2_1);
    k_conv2_slow<<<NN * HH, 256>>>();
    k_bn2<<<1, 256>>>(bn2_g, bn2_b);
    k_final<<<NPOS / 32, blk>>>(x, b1_2, p1a, b1_3, b2_2, p2a, b2_3, out);
}